// round 6
// baseline (speedup 1.0000x reference)
#include <cuda_runtime.h>
#include <math_constants.h>

#define NN 100000
#define NE 1000000
#define DD 64
#define ECAP 128
#define XST 132

// ---- static scratch ----
__device__ __align__(16) float d_h[NN * DD];
__device__ __align__(16) float d_x[NN * DD];
__device__ float d_asrc[NN];
__device__ float d_adst[NN];
__device__ int   d_cnt[NN];
__device__ int   d_ell[NN * ECAP];

#define FMA2(acc, a, b) \
    asm("fma.rn.f32x2 %0, %1, %2, %3;" : "=l"(acc) : "l"(a), "l"(b), "l"(acc))
#define PACKDUP(dst, v) \
    asm("mov.b64 %0, {%1, %1};" : "=l"(dst) : "f"(v))
// L2-only 16B load (random gather: ~0% L1 hit, skip L1 fill)
#define LDG_CG_V2U64(r, p) \
    asm volatile("ld.global.cg.v2.u64 {%0, %1}, [%2];" \
                 : "=l"((r).x), "=l"((r).y) : "l"(p))

union U64F2 { unsigned long long u; float f[2]; };

// ================= adjacency build =================

__global__ void zero_k() {
    int i = blockIdx.x * blockDim.x + threadIdx.x;
    if (i < NN) d_cnt[i] = 0;
}

__global__ void ell_k(const int* __restrict__ src, const int* __restrict__ dst) {
    int e = blockIdx.x * blockDim.x + threadIdx.x;
    if (e < NE) {
        int d = dst[e];
        int slot = atomicAdd(&d_cnt[d], 1);
        if (slot < ECAP) d_ell[d * ECAP + slot] = src[e];
    }
}

// ================= GEMM h = x @ W (FFMA2), fused attention logits ==============
// 128x64 tile, 128 threads, 8x8 per thread (1.0 B smem / FMA), stride-132.

__global__ __launch_bounds__(128) void gemm_attn_k(
        const float* __restrict__ x_ext, int use_internal,
        const float* __restrict__ W,
        const float* __restrict__ att_s, const float* __restrict__ att_d)
{
    const float* __restrict__ x = use_internal ? d_x : x_ext;
    __shared__ __align__(16) float ws[64 * 64];     // 16 KB
    __shared__ __align__(16) float xsT[64 * XST];   // 33.8 KB
    int tid  = threadIdx.x;
    int row0 = blockIdx.x * 128;

    for (int i = tid; i < 1024; i += 128)
        ((float4*)ws)[i] = ((const float4*)W)[i];
    for (int i = tid; i < 2048; i += 128) {
        int r = i >> 4, c4 = i & 15;
        float4 v = make_float4(0.f, 0.f, 0.f, 0.f);
        int gr = row0 + r;
        if (gr < NN) v = ((const float4*)x)[gr * 16 + c4];
        int c = c4 * 4;
        xsT[(c + 0) * XST + r] = v.x;
        xsT[(c + 1) * XST + r] = v.y;
        xsT[(c + 2) * XST + r] = v.z;
        xsT[(c + 3) * XST + r] = v.w;
    }
    __syncthreads();

    int tx = (tid & 7) * 8;          // 8 cols
    int ty = (tid >> 3) * 8;         // 8 rows

    unsigned long long acc[8][4];
#pragma unroll
    for (int i = 0; i < 8; i++)
#pragma unroll
        for (int m = 0; m < 4; m++) acc[i][m] = 0ull;

#pragma unroll 4
    for (int k = 0; k < 64; k++) {
        float4 xa = *(const float4*)&xsT[k * XST + ty];
        float4 xb = *(const float4*)&xsT[k * XST + ty + 4];
        ulonglong2 wA = *(const ulonglong2*)&ws[k * 64 + tx];
        ulonglong2 wB = *(const ulonglong2*)&ws[k * 64 + tx + 4];
        float xv[8] = {xa.x, xa.y, xa.z, xa.w, xb.x, xb.y, xb.z, xb.w};
#pragma unroll
        for (int i = 0; i < 8; i++) {
            unsigned long long xp;
            PACKDUP(xp, xv[i]);
            FMA2(acc[i][0], xp, wA.x);
            FMA2(acc[i][1], xp, wA.y);
            FMA2(acc[i][2], xp, wB.x);
            FMA2(acc[i][3], xp, wB.y);
        }
    }

    float4 asA = ((const float4*)att_s)[(tid & 7) * 2];
    float4 asB = ((const float4*)att_s)[(tid & 7) * 2 + 1];
    float4 adA = ((const float4*)att_d)[(tid & 7) * 2];
    float4 adB = ((const float4*)att_d)[(tid & 7) * 2 + 1];

#pragma unroll
    for (int i = 0; i < 8; i++) {
        U64F2 u0, u1, u2, u3;
        u0.u = acc[i][0]; u1.u = acc[i][1]; u2.u = acc[i][2]; u3.u = acc[i][3];
        float o0 = u0.f[0], o1 = u0.f[1], o2 = u1.f[0], o3 = u1.f[1];
        float o4 = u2.f[0], o5 = u2.f[1], o6 = u3.f[0], o7 = u3.f[1];

        float ps = o0*asA.x + o1*asA.y + o2*asA.z + o3*asA.w
                 + o4*asB.x + o5*asB.y + o6*asB.z + o7*asB.w;
        float pd = o0*adA.x + o1*adA.y + o2*adA.z + o3*adA.w
                 + o4*adB.x + o5*adB.y + o6*adB.z + o7*adB.w;
#pragma unroll
        for (int off = 4; off; off >>= 1) {
            ps += __shfl_xor_sync(0xffffffffu, ps, off, 8);
            pd += __shfl_xor_sync(0xffffffffu, pd, off, 8);
        }
        int gr = row0 + ty + i;
        if (gr < NN) {
            *(float4*)&d_h[gr * 64 + tx]     = make_float4(o0, o1, o2, o3);
            *(float4*)&d_h[gr * 64 + tx + 4] = make_float4(o4, o5, o6, o7);
            if ((tid & 7) == 0) { d_asrc[gr] = ps; d_adst[gr] = pd; }
        }
    }
}

// ================= segment softmax + weighted gather (warp per node) ===========
// 16 edges / iter: 8 independent L2-direct LDG.128 per lane in flight.

__global__ __launch_bounds__(256) void aggregate_k(
        const float* __restrict__ bias, float* __restrict__ out_ext, int to_internal)
{
    __shared__ float2 sew[8][32];
    float* __restrict__ out = to_internal ? d_x : out_ext;
    int w    = threadIdx.x >> 5;
    int lane = threadIdx.x & 31;
    int wid  = blockIdx.x * 8 + w;
    if (wid >= NN) return;

    int deg = d_cnt[wid];
    deg = deg > ECAP ? ECAP : deg;
    int half = lane >> 4, li = lane & 15;
    float4 b4 = ((const float4*)bias)[li];
    float4* op = (float4*)out + wid * 16 + li;

    if (deg == 0) { if (half == 0) *op = b4; return; }
    float adv = d_adst[wid];
    const int* row = d_ell + wid * ECAP;

    if (deg <= 32) {
        int idx = lane < deg ? lane : deg - 1;
        int s = row[idx];
        float e = d_asrc[s] + adv;
        e = e > 0.f ? e : 0.2f * e;
        float mx = lane < deg ? e : -CUDART_INF_F;
#pragma unroll
        for (int off = 16; off; off >>= 1)
            mx = fmaxf(mx, __shfl_xor_sync(0xffffffffu, mx, off));
        float wt = lane < deg ? __expf(e - mx) : 0.f;
        sew[w][lane] = make_float2(__int_as_float(s), wt);
        __syncwarp();

        unsigned long long a0 = 0ull, a1 = 0ull;
        float den = 0.f;
        int iters = (deg + 15) >> 4;
        for (int it = 0; it < iters; it++) {
            int base = it * 16 + half * 8;
            float2 p[8];
            ulonglong2 h[8];
#pragma unroll
            for (int q = 0; q < 8; q++) p[q] = sew[w][base + q];
#pragma unroll
            for (int q = 0; q < 8; q++) {
                const ulonglong2* ptr =
                    (const ulonglong2*)(d_h + __float_as_int(p[q].x) * 64) + li;
                LDG_CG_V2U64(h[q], ptr);
            }
#pragma unroll
            for (int q = 0; q < 8; q++) {
                den += p[q].y;
                unsigned long long wq;
                PACKDUP(wq, p[q].y);
                FMA2(a0, wq, h[q].x);
                FMA2(a1, wq, h[q].y);
            }
        }
        U64F2 ua, ub;
        ua.u = a0; ub.u = a1;
        float f0 = ua.f[0], f1 = ua.f[1], f2 = ub.f[0], f3 = ub.f[1];
        f0  += __shfl_xor_sync(0xffffffffu, f0, 16);
        f1  += __shfl_xor_sync(0xffffffffu, f1, 16);
        f2  += __shfl_xor_sync(0xffffffffu, f2, 16);
        f3  += __shfl_xor_sync(0xffffffffu, f3, 16);
        den += __shfl_xor_sync(0xffffffffu, den, 16);
        if (half == 0) {
            float inv = 1.f / (den + 1e-16f);
            float4 r;
            r.x = f0 * inv + b4.x;
            r.y = f1 * inv + b4.y;
            r.z = f2 * inv + b4.z;
            r.w = f3 * inv + b4.w;
            *op = r;
        }
    } else {
        // essentially-never path (Poisson(10) degree > 32)
        float mx = -CUDART_INF_F;
        for (int j = lane; j < deg; j += 32) {
            float e = d_asrc[row[j]] + adv;
            e = e > 0.f ? e : 0.2f * e;
            mx = fmaxf(mx, e);
        }
#pragma unroll
        for (int off = 16; off; off >>= 1)
            mx = fmaxf(mx, __shfl_xor_sync(0xffffffffu, mx, off));
        float sm = 0.f;
        for (int j = lane; j < deg; j += 32) {
            float e = d_asrc[row[j]] + adv;
            e = e > 0.f ? e : 0.2f * e;
            sm += __expf(e - mx);
        }
#pragma unroll
        for (int off = 16; off; off >>= 1)
            sm += __shfl_xor_sync(0xffffffffu, sm, off);
        float inv = 1.f / (sm + 1e-16f);

        float4 acc = make_float4(0.f, 0.f, 0.f, 0.f);
        for (int j = half; j < deg; j += 2) {
            int s = row[j];
            float e = d_asrc[s] + adv;
            e = e > 0.f ? e : 0.2f * e;
            float wt = __expf(e - mx);
            float4 hv = ((const float4*)(d_h + s * 64))[li];
            acc.x += wt * hv.x; acc.y += wt * hv.y;
            acc.z += wt * hv.z; acc.w += wt * hv.w;
        }
        acc.x += __shfl_xor_sync(0xffffffffu, acc.x, 16);
        acc.y += __shfl_xor_sync(0xffffffffu, acc.y, 16);
        acc.z += __shfl_xor_sync(0xffffffffu, acc.z, 16);
        acc.w += __shfl_xor_sync(0xffffffffu, acc.w, 16);
        if (half == 0) {
            float4 r;
            r.x = acc.x * inv + b4.x;
            r.y = acc.y * inv + b4.y;
            r.z = acc.z * inv + b4.z;
            r.w = acc.w * inv + b4.w;
            *op = r;
        }
    }
}

// ================= launch =================

extern "C" void kernel_launch(void* const* d_in, const int* in_sizes, int n_in,
                              void* d_out, int out_size)
{
    const float* g     = (const float*)d_in[0];
    const int*   ei    = (const int*)  d_in[1];
    const float* W     = (const float*)d_in[2];
    const float* att_s = (const float*)d_in[3];
    const float* att_d = (const float*)d_in[4];
    const float* bias  = (const float*)d_in[5];
    float* out = (float*)d_out;

    const int* src = ei;
    const int* dst = ei + NE;

    zero_k<<<(NN + 255) / 256, 256>>>();
    ell_k<<<(NE + 255) / 256, 256>>>(src, dst);

    const int gemm_blocks = (NN + 127) / 128;   // 782
    const int agg_blocks  = (NN + 7) / 8;       // 12500

    for (int L = 0; L < 4; L++) {
        gemm_attn_k<<<gemm_blocks, 128>>>(L == 0 ? g : nullptr, L == 0 ? 0 : 1,
                                          W, att_s, att_d);
        aggregate_k<<<agg_blocks, 256>>>(bias, L == 3 ? out : nullptr,
                                         L == 3 ? 0 : 1);
    }
}

// round 7
// speedup vs baseline: 1.1286x; 1.1286x over previous
#include <cuda_runtime.h>
#include <math_constants.h>

#define NN 100000
#define NE 1000000
#define DD 64
#define ECAP 128
#define XST 132

// ---- static scratch ----
__device__ __align__(16) float d_h[NN * DD];
__device__ __align__(16) float d_x[NN * DD];
__device__ float d_asrc[NN];
__device__ float d_adst[NN];
__device__ int   d_cnt[NN];
__device__ int   d_ell[NN * ECAP];

#define FMA2(acc, a, b) \
    asm("fma.rn.f32x2 %0, %1, %2, %3;" : "=l"(acc) : "l"(a), "l"(b), "l"(acc))
#define PACKDUP(dst, v) \
    asm("mov.b64 %0, {%1, %1};" : "=l"(dst) : "f"(v))

union U64F2 { unsigned long long u; float f[2]; };

// ================= adjacency build =================

__global__ void zero_k() {
    int i = blockIdx.x * blockDim.x + threadIdx.x;
    if (i < NN) d_cnt[i] = 0;
}

__global__ void ell_k(const int* __restrict__ src, const int* __restrict__ dst) {
    int e = blockIdx.x * blockDim.x + threadIdx.x;
    if (e < NE) {
        int d = dst[e];
        int slot = atomicAdd(&d_cnt[d], 1);
        if (slot < ECAP) d_ell[d * ECAP + slot] = src[e];
    }
}

// ================= GEMM h = x @ W (FFMA2), fused attention logits ==============
// 128x64 tile, 256 threads, 8 rows x 4 cols per thread.
// Accumulators packed along ROW PAIRS: the f32x2 x-operand is a free 16B LDS
// of adjacent rows in the transposed tile; only W needs PACKDUP (4/k, not 8/k).

__global__ __launch_bounds__(256) void gemm_attn_k(
        const float* __restrict__ x_ext, int use_internal,
        const float* __restrict__ W,
        const float* __restrict__ att_s, const float* __restrict__ att_d)
{
    const float* __restrict__ x = use_internal ? d_x : x_ext;
    __shared__ __align__(16) float ws[64 * 64];     // 16 KB
    __shared__ __align__(16) float xsT[64 * XST];   // 33.8 KB
    int tid  = threadIdx.x;
    int row0 = blockIdx.x * 128;

    for (int i = tid; i < 1024; i += 256)
        ((float4*)ws)[i] = ((const float4*)W)[i];
    for (int i = tid; i < 2048; i += 256) {
        int r = i >> 4, c4 = i & 15;
        float4 v = make_float4(0.f, 0.f, 0.f, 0.f);
        int gr = row0 + r;
        if (gr < NN) v = ((const float4*)x)[gr * 16 + c4];
        int c = c4 * 4;
        xsT[(c + 0) * XST + r] = v.x;
        xsT[(c + 1) * XST + r] = v.y;
        xsT[(c + 2) * XST + r] = v.z;
        xsT[(c + 3) * XST + r] = v.w;
    }
    __syncthreads();

    int tx = (tid & 15) * 4;         // 4 cols
    int ty = (tid >> 4) * 8;         // 8 rows (4 row-pairs)

    unsigned long long acc[4][4];    // [row-pair][col]
#pragma unroll
    for (int rp = 0; rp < 4; rp++)
#pragma unroll
        for (int c = 0; c < 4; c++) acc[rp][c] = 0ull;

#pragma unroll 8
    for (int k = 0; k < 64; k++) {
        ulonglong2 xpA = *(const ulonglong2*)&xsT[k * XST + ty];      // pairs (r0,r1),(r2,r3)
        ulonglong2 xpB = *(const ulonglong2*)&xsT[k * XST + ty + 4];  // pairs (r4,r5),(r6,r7)
        float4 wv = *(const float4*)&ws[k * 64 + tx];
        unsigned long long w0, w1, w2, w3;
        PACKDUP(w0, wv.x); PACKDUP(w1, wv.y);
        PACKDUP(w2, wv.z); PACKDUP(w3, wv.w);
        unsigned long long xp[4] = {xpA.x, xpA.y, xpB.x, xpB.y};
#pragma unroll
        for (int rp = 0; rp < 4; rp++) {
            FMA2(acc[rp][0], xp[rp], w0);
            FMA2(acc[rp][1], xp[rp], w1);
            FMA2(acc[rp][2], xp[rp], w2);
            FMA2(acc[rp][3], xp[rp], w3);
        }
    }

    float4 as4 = ((const float4*)att_s)[tid & 15];
    float4 ad4 = ((const float4*)att_d)[tid & 15];

#pragma unroll
    for (int rp = 0; rp < 4; rp++) {
        U64F2 c0, c1, c2, c3;
        c0.u = acc[rp][0]; c1.u = acc[rp][1];
        c2.u = acc[rp][2]; c3.u = acc[rp][3];
#pragma unroll
        for (int h = 0; h < 2; h++) {
            float o0 = c0.f[h], o1 = c1.f[h], o2 = c2.f[h], o3 = c3.f[h];
            float ps = o0*as4.x + o1*as4.y + o2*as4.z + o3*as4.w;
            float pd = o0*ad4.x + o1*ad4.y + o2*ad4.z + o3*ad4.w;
#pragma unroll
            for (int off = 8; off; off >>= 1) {
                ps += __shfl_xor_sync(0xffffffffu, ps, off, 16);
                pd += __shfl_xor_sync(0xffffffffu, pd, off, 16);
            }
            int gr = row0 + ty + rp * 2 + h;
            if (gr < NN) {
                *(float4*)&d_h[gr * 64 + tx] = make_float4(o0, o1, o2, o3);
                if ((tid & 15) == 0) { d_asrc[gr] = ps; d_adst[gr] = pd; }
            }
        }
    }
}

// ================= segment softmax + weighted gather (warp per node) ===========
// R5 version verbatim: denominator folded into gather, 8 blocks/SM reg cap.

__global__ __launch_bounds__(256, 8) void aggregate_k(
        const float* __restrict__ bias, float* __restrict__ out_ext, int to_internal)
{
    __shared__ float2 sew[8][32];
    float* __restrict__ out = to_internal ? d_x : out_ext;
    int w    = threadIdx.x >> 5;
    int lane = threadIdx.x & 31;
    int wid  = blockIdx.x * 8 + w;
    if (wid >= NN) return;

    int deg = d_cnt[wid];
    deg = deg > ECAP ? ECAP : deg;
    int half = lane >> 4, li = lane & 15;
    float4 b4 = ((const float4*)bias)[li];
    float4* op = (float4*)out + wid * 16 + li;

    if (deg == 0) { if (half == 0) *op = b4; return; }
    float adv = d_adst[wid];
    const int* row = d_ell + wid * ECAP;

    if (deg <= 32) {
        int idx = lane < deg ? lane : deg - 1;
        int s = row[idx];
        float e = d_asrc[s] + adv;
        e = e > 0.f ? e : 0.2f * e;
        float mx = lane < deg ? e : -CUDART_INF_F;
#pragma unroll
        for (int off = 16; off; off >>= 1)
            mx = fmaxf(mx, __shfl_xor_sync(0xffffffffu, mx, off));
        float wt = lane < deg ? __expf(e - mx) : 0.f;
        sew[w][lane] = make_float2(__int_as_float(s), wt);
        __syncwarp();

        unsigned long long a0 = 0ull, a1 = 0ull;
        float den = 0.f;
        int iters = (deg + 7) >> 3;
        for (int it = 0; it < iters; it++) {
            int base = it * 8 + half * 4;
            float2 p0 = sew[w][base + 0];
            float2 p1 = sew[w][base + 1];
            float2 p2 = sew[w][base + 2];
            float2 p3 = sew[w][base + 3];
            ulonglong2 h0 = ((const ulonglong2*)(d_h + __float_as_int(p0.x) * 64))[li];
            ulonglong2 h1 = ((const ulonglong2*)(d_h + __float_as_int(p1.x) * 64))[li];
            ulonglong2 h2 = ((const ulonglong2*)(d_h + __float_as_int(p2.x) * 64))[li];
            ulonglong2 h3 = ((const ulonglong2*)(d_h + __float_as_int(p3.x) * 64))[li];
            den += (p0.y + p1.y) + (p2.y + p3.y);
            unsigned long long w0, w1, w2, w3;
            PACKDUP(w0, p0.y); PACKDUP(w1, p1.y);
            PACKDUP(w2, p2.y); PACKDUP(w3, p3.y);
            FMA2(a0, w0, h0.x); FMA2(a1, w0, h0.y);
            FMA2(a0, w1, h1.x); FMA2(a1, w1, h1.y);
            FMA2(a0, w2, h2.x); FMA2(a1, w2, h2.y);
            FMA2(a0, w3, h3.x); FMA2(a1, w3, h3.y);
        }
        U64F2 ua, ub;
        ua.u = a0; ub.u = a1;
        float f0 = ua.f[0], f1 = ua.f[1], f2 = ub.f[0], f3 = ub.f[1];
        f0  += __shfl_xor_sync(0xffffffffu, f0, 16);
        f1  += __shfl_xor_sync(0xffffffffu, f1, 16);
        f2  += __shfl_xor_sync(0xffffffffu, f2, 16);
        f3  += __shfl_xor_sync(0xffffffffu, f3, 16);
        den += __shfl_xor_sync(0xffffffffu, den, 16);
        if (half == 0) {
            float inv = 1.f / (den + 1e-16f);
            float4 r;
            r.x = f0 * inv + b4.x;
            r.y = f1 * inv + b4.y;
            r.z = f2 * inv + b4.z;
            r.w = f3 * inv + b4.w;
            *op = r;
        }
    } else {
        // essentially-never path (Poisson(10) degree > 32)
        float mx = -CUDART_INF_F;
        for (int j = lane; j < deg; j += 32) {
            float e = d_asrc[row[j]] + adv;
            e = e > 0.f ? e : 0.2f * e;
            mx = fmaxf(mx, e);
        }
#pragma unroll
        for (int off = 16; off; off >>= 1)
            mx = fmaxf(mx, __shfl_xor_sync(0xffffffffu, mx, off));
        float sm = 0.f;
        for (int j = lane; j < deg; j += 32) {
            float e = d_asrc[row[j]] + adv;
            e = e > 0.f ? e : 0.2f * e;
            sm += __expf(e - mx);
        }
#pragma unroll
        for (int off = 16; off; off >>= 1)
            sm += __shfl_xor_sync(0xffffffffu, sm, off);
        float inv = 1.f / (sm + 1e-16f);

        float4 acc = make_float4(0.f, 0.f, 0.f, 0.f);
        for (int j = half; j < deg; j += 2) {
            int s = row[j];
            float e = d_asrc[s] + adv;
            e = e > 0.f ? e : 0.2f * e;
            float wt = __expf(e - mx);
            float4 hv = ((const float4*)(d_h + s * 64))[li];
            acc.x += wt * hv.x; acc.y += wt * hv.y;
            acc.z += wt * hv.z; acc.w += wt * hv.w;
        }
        acc.x += __shfl_xor_sync(0xffffffffu, acc.x, 16);
        acc.y += __shfl_xor_sync(0xffffffffu, acc.y, 16);
        acc.z += __shfl_xor_sync(0xffffffffu, acc.z, 16);
        acc.w += __shfl_xor_sync(0xffffffffu, acc.w, 16);
        if (half == 0) {
            float4 r;
            r.x = acc.x * inv + b4.x;
            r.y = acc.y * inv + b4.y;
            r.z = acc.z * inv + b4.z;
            r.w = acc.w * inv + b4.w;
            *op = r;
        }
    }
}

// ================= launch =================

extern "C" void kernel_launch(void* const* d_in, const int* in_sizes, int n_in,
                              void* d_out, int out_size)
{
    const float* g     = (const float*)d_in[0];
    const int*   ei    = (const int*)  d_in[1];
    const float* W     = (const float*)d_in[2];
    const float* att_s = (const float*)d_in[3];
    const float* att_d = (const float*)d_in[4];
    const float* bias  = (const float*)d_in[5];
    float* out = (float*)d_out;

    const int* src = ei;
    const int* dst = ei + NE;

    zero_k<<<(NN + 255) / 256, 256>>>();
    ell_k<<<(NE + 255) / 256, 256>>>(src, dst);

    const int gemm_blocks = (NN + 127) / 128;   // 782
    const int agg_blocks  = (NN + 7) / 8;       // 12500

    for (int L = 0; L < 4; L++) {
        gemm_attn_k<<<gemm_blocks, 256>>>(L == 0 ? g : nullptr, L == 0 ? 0 : 1,
                                          W, att_s, att_d);
        aggregate_k<<<agg_blocks, 256>>>(bias, L == 3 ? out : nullptr,
                                         L == 3 ? 0 : 1);
    }
}

// round 8
// speedup vs baseline: 1.2366x; 1.0957x over previous
#include <cuda_runtime.h>
#include <cuda_fp16.h>
#include <math_constants.h>

#define NN 100000
#define NE 1000000
#define DD 64
#define ECAP 128
#define XST 132

// ---- static scratch ----
__device__ __align__(16) __half d_hh[NN * DD];  // fp16 projected features (gather operand)
__device__ __align__(16) float  d_x[NN * DD];   // fp32 layer ping buffer
__device__ float d_asrc[NN];
__device__ float d_adst[NN];
__device__ int   d_cnt[NN];
__device__ int   d_ell[NN * ECAP];

#define FMA2(acc, a, b) \
    asm("fma.rn.f32x2 %0, %1, %2, %3;" : "=l"(acc) : "l"(a), "l"(b), "l"(acc))
#define PACKDUP(dst, v) \
    asm("mov.b64 %0, {%1, %1};" : "=l"(dst) : "f"(v))

union U64F2 { unsigned long long u; float f[2]; };

// ================= adjacency build =================

__global__ void zero_k() {
    int i = blockIdx.x * blockDim.x + threadIdx.x;
    if (i < NN) d_cnt[i] = 0;
}

__global__ void ell_k(const int* __restrict__ src, const int* __restrict__ dst) {
    int e = blockIdx.x * blockDim.x + threadIdx.x;
    if (e < NE) {
        int d = dst[e];
        int slot = atomicAdd(&d_cnt[d], 1);
        if (slot < ECAP) d_ell[d * ECAP + slot] = src[e];
    }
}

// ================= GEMM h = x @ W (FFMA2, fp32), fused logits; h stored fp16 ===

__global__ __launch_bounds__(256) void gemm_attn_k(
        const float* __restrict__ x_ext, int use_internal,
        const float* __restrict__ W,
        const float* __restrict__ att_s, const float* __restrict__ att_d)
{
    const float* __restrict__ x = use_internal ? d_x : x_ext;
    __shared__ __align__(16) float ws[64 * 64];
    __shared__ __align__(16) float xsT[64 * XST];
    int tid  = threadIdx.x;
    int row0 = blockIdx.x * 128;

    for (int i = tid; i < 1024; i += 256)
        ((float4*)ws)[i] = ((const float4*)W)[i];
    for (int i = tid; i < 2048; i += 256) {
        int r = i >> 4, c4 = i & 15;
        float4 v = make_float4(0.f, 0.f, 0.f, 0.f);
        int gr = row0 + r;
        if (gr < NN) v = ((const float4*)x)[gr * 16 + c4];
        int c = c4 * 4;
        xsT[(c + 0) * XST + r] = v.x;
        xsT[(c + 1) * XST + r] = v.y;
        xsT[(c + 2) * XST + r] = v.z;
        xsT[(c + 3) * XST + r] = v.w;
    }
    __syncthreads();

    int tx = (tid & 15) * 4;
    int ty = (tid >> 4) * 8;

    unsigned long long acc[4][4];
#pragma unroll
    for (int rp = 0; rp < 4; rp++)
#pragma unroll
        for (int c = 0; c < 4; c++) acc[rp][c] = 0ull;

#pragma unroll 8
    for (int k = 0; k < 64; k++) {
        ulonglong2 xpA = *(const ulonglong2*)&xsT[k * XST + ty];
        ulonglong2 xpB = *(const ulonglong2*)&xsT[k * XST + ty + 4];
        float4 wv = *(const float4*)&ws[k * 64 + tx];
        unsigned long long w0, w1, w2, w3;
        PACKDUP(w0, wv.x); PACKDUP(w1, wv.y);
        PACKDUP(w2, wv.z); PACKDUP(w3, wv.w);
        unsigned long long xp[4] = {xpA.x, xpA.y, xpB.x, xpB.y};
#pragma unroll
        for (int rp = 0; rp < 4; rp++) {
            FMA2(acc[rp][0], xp[rp], w0);
            FMA2(acc[rp][1], xp[rp], w1);
            FMA2(acc[rp][2], xp[rp], w2);
            FMA2(acc[rp][3], xp[rp], w3);
        }
    }

    float4 as4 = ((const float4*)att_s)[tid & 15];
    float4 ad4 = ((const float4*)att_d)[tid & 15];

#pragma unroll
    for (int rp = 0; rp < 4; rp++) {
        U64F2 c0, c1, c2, c3;
        c0.u = acc[rp][0]; c1.u = acc[rp][1];
        c2.u = acc[rp][2]; c3.u = acc[rp][3];
#pragma unroll
        for (int h = 0; h < 2; h++) {
            float o0 = c0.f[h], o1 = c1.f[h], o2 = c2.f[h], o3 = c3.f[h];
            float ps = o0*as4.x + o1*as4.y + o2*as4.z + o3*as4.w;
            float pd = o0*ad4.x + o1*ad4.y + o2*ad4.z + o3*ad4.w;
#pragma unroll
            for (int off = 8; off; off >>= 1) {
                ps += __shfl_xor_sync(0xffffffffu, ps, off, 16);
                pd += __shfl_xor_sync(0xffffffffu, pd, off, 16);
            }
            int gr = row0 + ty + rp * 2 + h;
            if (gr < NN) {
                __half2 p0 = __floats2half2_rn(o0, o1);
                __half2 p1 = __floats2half2_rn(o2, o3);
                uint2 pk;
                pk.x = *(unsigned*)&p0;
                pk.y = *(unsigned*)&p1;
                *(uint2*)&d_hh[gr * 64 + tx] = pk;
                if ((tid & 15) == 0) { d_asrc[gr] = ps; d_adst[gr] = pd; }
            }
        }
    }
}

// ================= segment softmax + weighted gather (warp per node) ===========
// fp16 rows: 1 L1 line per edge. fp32 weights/accumulation.

__global__ __launch_bounds__(256, 8) void aggregate_k(
        const float* __restrict__ bias, float* __restrict__ out_ext, int to_internal)
{
    __shared__ float2 sew[8][32];
    float* __restrict__ out = to_internal ? d_x : out_ext;
    int w    = threadIdx.x >> 5;
    int lane = threadIdx.x & 31;
    int wid  = blockIdx.x * 8 + w;
    if (wid >= NN) return;

    int deg = d_cnt[wid];
    deg = deg > ECAP ? ECAP : deg;
    int half = lane >> 4, li = lane & 15;
    float4 b4 = ((const float4*)bias)[li];
    float4* op = (float4*)out + wid * 16 + li;

    if (deg == 0) { if (half == 0) *op = b4; return; }
    float adv = d_adst[wid];
    const int* row = d_ell + wid * ECAP;

    if (deg <= 32) {
        int idx = lane < deg ? lane : deg - 1;
        int s = row[idx];
        float e = d_asrc[s] + adv;
        e = e > 0.f ? e : 0.2f * e;
        float mx = lane < deg ? e : -CUDART_INF_F;
#pragma unroll
        for (int off = 16; off; off >>= 1)
            mx = fmaxf(mx, __shfl_xor_sync(0xffffffffu, mx, off));
        float wt = lane < deg ? __expf(e - mx) : 0.f;
        sew[w][lane] = make_float2(__int_as_float(s), wt);
        __syncwarp();

        float ax = 0.f, ay = 0.f, az = 0.f, aw = 0.f;
        float den = 0.f;
        int iters = (deg + 7) >> 3;
        for (int it = 0; it < iters; it++) {
            int base = it * 8 + half * 4;
            float2 p0 = sew[w][base + 0];
            float2 p1 = sew[w][base + 1];
            float2 p2 = sew[w][base + 2];
            float2 p3 = sew[w][base + 3];
            uint2 h0 = ((const uint2*)(d_hh + __float_as_int(p0.x) * 64))[li];
            uint2 h1 = ((const uint2*)(d_hh + __float_as_int(p1.x) * 64))[li];
            uint2 h2 = ((const uint2*)(d_hh + __float_as_int(p2.x) * 64))[li];
            uint2 h3 = ((const uint2*)(d_hh + __float_as_int(p3.x) * 64))[li];
            den += (p0.y + p1.y) + (p2.y + p3.y);
            {
                float2 lo = __half22float2(*(__half2*)&h0.x);
                float2 hi = __half22float2(*(__half2*)&h0.y);
                ax += p0.y * lo.x; ay += p0.y * lo.y;
                az += p0.y * hi.x; aw += p0.y * hi.y;
            }
            {
                float2 lo = __half22float2(*(__half2*)&h1.x);
                float2 hi = __half22float2(*(__half2*)&h1.y);
                ax += p1.y * lo.x; ay += p1.y * lo.y;
                az += p1.y * hi.x; aw += p1.y * hi.y;
            }
            {
                float2 lo = __half22float2(*(__half2*)&h2.x);
                float2 hi = __half22float2(*(__half2*)&h2.y);
                ax += p2.y * lo.x; ay += p2.y * lo.y;
                az += p2.y * hi.x; aw += p2.y * hi.y;
            }
            {
                float2 lo = __half22float2(*(__half2*)&h3.x);
                float2 hi = __half22float2(*(__half2*)&h3.y);
                ax += p3.y * lo.x; ay += p3.y * lo.y;
                az += p3.y * hi.x; aw += p3.y * hi.y;
            }
        }
        ax  += __shfl_xor_sync(0xffffffffu, ax, 16);
        ay  += __shfl_xor_sync(0xffffffffu, ay, 16);
        az  += __shfl_xor_sync(0xffffffffu, az, 16);
        aw  += __shfl_xor_sync(0xffffffffu, aw, 16);
        den += __shfl_xor_sync(0xffffffffu, den, 16);
        if (half == 0) {
            float inv = 1.f / (den + 1e-16f);
            float4 r;
            r.x = ax * inv + b4.x;
            r.y = ay * inv + b4.y;
            r.z = az * inv + b4.z;
            r.w = aw * inv + b4.w;
            *op = r;
        }
    } else {
        // essentially-never path (Poisson(10) degree > 32)
        float mx = -CUDART_INF_F;
        for (int j = lane; j < deg; j += 32) {
            float e = d_asrc[row[j]] + adv;
            e = e > 0.f ? e : 0.2f * e;
            mx = fmaxf(mx, e);
        }
#pragma unroll
        for (int off = 16; off; off >>= 1)
            mx = fmaxf(mx, __shfl_xor_sync(0xffffffffu, mx, off));
        float sm = 0.f;
        for (int j = lane; j < deg; j += 32) {
            float e = d_asrc[row[j]] + adv;
            e = e > 0.f ? e : 0.2f * e;
            sm += __expf(e - mx);
        }
#pragma unroll
        for (int off = 16; off; off >>= 1)
            sm += __shfl_xor_sync(0xffffffffu, sm, off);
        float inv = 1.f / (sm + 1e-16f);

        float4 acc = make_float4(0.f, 0.f, 0.f, 0.f);
        for (int j = half; j < deg; j += 2) {
            int s = row[j];
            float e = d_asrc[s] + adv;
            e = e > 0.f ? e : 0.2f * e;
            float wt = __expf(e - mx);
            uint2 hv = ((const uint2*)(d_hh + s * 64))[li];
            float2 lo = __half22float2(*(__half2*)&hv.x);
            float2 hi = __half22float2(*(__half2*)&hv.y);
            acc.x += wt * lo.x; acc.y += wt * lo.y;
            acc.z += wt * hi.x; acc.w += wt * hi.y;
        }
        acc.x += __shfl_xor_sync(0xffffffffu, acc.x, 16);
        acc.y += __shfl_xor_sync(0xffffffffu, acc.y, 16);
        acc.z += __shfl_xor_sync(0xffffffffu, acc.z, 16);
        acc.w += __shfl_xor_sync(0xffffffffu, acc.w, 16);
        if (half == 0) {
            float4 r;
            r.x = acc.x * inv + b4.x;
            r.y = acc.y * inv + b4.y;
            r.z = acc.z * inv + b4.z;
            r.w = acc.w * inv + b4.w;
            *op = r;
        }
    }
}

// ================= launch =================

extern "C" void kernel_launch(void* const* d_in, const int* in_sizes, int n_in,
                              void* d_out, int out_size)
{
    const float* g     = (const float*)d_in[0];
    const int*   ei    = (const int*)  d_in[1];
    const float* W     = (const float*)d_in[2];
    const float* att_s = (const float*)d_in[3];
    const float* att_d = (const float*)d_in[4];
    const float* bias  = (const float*)d_in[5];
    float* out = (float*)d_out;

    const int* src = ei;
    const int* dst = ei + NE;

    zero_k<<<(NN + 255) / 256, 256>>>();
    ell_k<<<(NE + 255) / 256, 256>>>(src, dst);

    const int gemm_blocks = (NN + 127) / 128;   // 782
    const int agg_blocks  = (NN + 7) / 8;       // 12500

    for (int L = 0; L < 4; L++) {
        gemm_attn_k<<<gemm_blocks, 256>>>(L == 0 ? g : nullptr, L == 0 ? 0 : 1,
                                          W, att_s, att_d);
        aggregate_k<<<agg_blocks, 256>>>(bias, L == 3 ? out : nullptr,
                                         L == 3 ? 0 : 1);
    }
}

// round 10
// speedup vs baseline: 1.5149x; 1.2250x over previous
#include <cuda_runtime.h>
#include <cuda_fp16.h>
#include <math_constants.h>

#define NN 100000
#define NE 1000000
#define DD 64
#define ECAP 128
#define XST 132

// ---- static scratch ----
__device__ __align__(16) __half d_hh[NN * DD];  // fp16 projected features
__device__ __align__(16) float  d_x[NN * DD];   // fp32 layer ping buffer
__device__ float d_asrc[NN];
__device__ float d_adst[NN];
__device__ int   d_cnt[NN];
__device__ int   d_ell[NN * ECAP];

#define FMA2(acc, a, b) \
    asm("fma.rn.f32x2 %0, %1, %2, %3;" : "=l"(acc) : "l"(a), "l"(b), "l"(acc))
#define PACKDUP(dst, v) \
    asm("mov.b64 %0, {%1, %1};" : "=l"(dst) : "f"(v))

union U64F2 { unsigned long long u; float f[2]; };

// ================= adjacency build =================

__global__ void zero_k() {
    int i = blockIdx.x * blockDim.x + threadIdx.x;
    if (i < NN) d_cnt[i] = 0;
}

__global__ void ell_k(const int* __restrict__ src, const int* __restrict__ dst) {
    int e = blockIdx.x * blockDim.x + threadIdx.x;
    if (e < NE) {
        int d = dst[e];
        int slot = atomicAdd(&d_cnt[d], 1);
        if (slot < ECAP) d_ell[d * ECAP + slot] = src[e];
    }
}

// ================= GEMM h = x @ W (FFMA2, fp32), fused logits; h stored fp16 ===

__global__ __launch_bounds__(256) void gemm_attn_k(
        const float* __restrict__ x_ext, int use_internal,
        const float* __restrict__ W,
        const float* __restrict__ att_s, const float* __restrict__ att_d)
{
    const float* __restrict__ x = use_internal ? d_x : x_ext;
    __shared__ __align__(16) float ws[64 * 64];
    __shared__ __align__(16) float xsT[64 * XST];
    int tid  = threadIdx.x;
    int row0 = blockIdx.x * 128;

    for (int i = tid; i < 1024; i += 256)
        ((float4*)ws)[i] = ((const float4*)W)[i];
    for (int i = tid; i < 2048; i += 256) {
        int r = i >> 4, c4 = i & 15;
        float4 v = make_float4(0.f, 0.f, 0.f, 0.f);
        int gr = row0 + r;
        if (gr < NN) v = ((const float4*)x)[gr * 16 + c4];
        int c = c4 * 4;
        xsT[(c + 0) * XST + r] = v.x;
        xsT[(c + 1) * XST + r] = v.y;
        xsT[(c + 2) * XST + r] = v.z;
        xsT[(c + 3) * XST + r] = v.w;
    }
    __syncthreads();

    int tx = (tid & 15) * 4;
    int ty = (tid >> 4) * 8;

    unsigned long long acc[4][4];
#pragma unroll
    for (int rp = 0; rp < 4; rp++)
#pragma unroll
        for (int c = 0; c < 4; c++) acc[rp][c] = 0ull;

#pragma unroll 8
    for (int k = 0; k < 64; k++) {
        ulonglong2 xpA = *(const ulonglong2*)&xsT[k * XST + ty];
        ulonglong2 xpB = *(const ulonglong2*)&xsT[k * XST + ty + 4];
        float4 wv = *(const float4*)&ws[k * 64 + tx];
        unsigned long long w0, w1, w2, w3;
        PACKDUP(w0, wv.x); PACKDUP(w1, wv.y);
        PACKDUP(w2, wv.z); PACKDUP(w3, wv.w);
        unsigned long long xp[4] = {xpA.x, xpA.y, xpB.x, xpB.y};
#pragma unroll
        for (int rp = 0; rp < 4; rp++) {
            FMA2(acc[rp][0], xp[rp], w0);
            FMA2(acc[rp][1], xp[rp], w1);
            FMA2(acc[rp][2], xp[rp], w2);
            FMA2(acc[rp][3], xp[rp], w3);
        }
    }

    float4 as4 = ((const float4*)att_s)[tid & 15];
    float4 ad4 = ((const float4*)att_d)[tid & 15];

#pragma unroll
    for (int rp = 0; rp < 4; rp++) {
        U64F2 c0, c1, c2, c3;
        c0.u = acc[rp][0]; c1.u = acc[rp][1];
        c2.u = acc[rp][2]; c3.u = acc[rp][3];
#pragma unroll
        for (int h = 0; h < 2; h++) {
            float o0 = c0.f[h], o1 = c1.f[h], o2 = c2.f[h], o3 = c3.f[h];
            float ps = o0*as4.x + o1*as4.y + o2*as4.z + o3*as4.w;
            float pd = o0*ad4.x + o1*ad4.y + o2*ad4.z + o3*ad4.w;
#pragma unroll
            for (int off = 8; off; off >>= 1) {
                ps += __shfl_xor_sync(0xffffffffu, ps, off, 16);
                pd += __shfl_xor_sync(0xffffffffu, pd, off, 16);
            }
            int gr = row0 + ty + rp * 2 + h;
            if (gr < NN) {
                __half2 p0 = __floats2half2_rn(o0, o1);
                __half2 p1 = __floats2half2_rn(o2, o3);
                uint2 pk;
                pk.x = *(unsigned*)&p0;
                pk.y = *(unsigned*)&p1;
                *(uint2*)&d_hh[gr * 64 + tx] = pk;
                if ((tid & 15) == 0) { d_asrc[gr] = ps; d_adst[gr] = pd; }
            }
        }
    }
}

// ================= segment softmax + weighted gather (HALF-WARP per node) ======
// 16 lanes per node; lane owns 4 output dims end-to-end (no reduction shfls).
// 4-edge granularity; all shfls/syncs per-half masked.

__global__ __launch_bounds__(256, 8) void aggregate_k(
        const float* __restrict__ bias, float* __restrict__ out_ext, int to_internal)
{
    __shared__ float2 sew[8][2][32];
    float* __restrict__ out = to_internal ? d_x : out_ext;
    int w    = threadIdx.x >> 5;
    int lane = threadIdx.x & 31;
    int half = lane >> 4, li = lane & 15;
    unsigned hm = 0xFFFFu << (half * 16);
    int node = (blockIdx.x * 8 + w) * 2 + half;   // 6250*8*2 = 100000 exactly

    int deg = d_cnt[node];
    deg = deg > ECAP ? ECAP : deg;
    float4 b4 = ((const float4*)bias)[li];
    float4* op = (float4*)out + node * 16 + li;
    const int* row = d_ell + node * ECAP;

    if (deg <= 32) {
        float adv = d_adst[node];
        // logits round 1 (slots 0..15)
        int   s0 = row[li < deg ? li : (deg > 0 ? deg - 1 : 0)];
        float e0 = d_asrc[s0] + adv;
        e0 = e0 > 0.f ? e0 : 0.2f * e0;
        float mx = li < deg ? e0 : -CUDART_INF_F;
        int s1 = 0; float e1 = 0.f;
        if (deg > 16) {                      // round 2 (slots 16..31)
            int i2 = li + 16;
            s1 = row[i2 < deg ? i2 : deg - 1];
            e1 = d_asrc[s1] + adv;
            e1 = e1 > 0.f ? e1 : 0.2f * e1;
            if (i2 < deg) mx = fmaxf(mx, e1);
        }
#pragma unroll
        for (int off = 8; off; off >>= 1)
            mx = fmaxf(mx, __shfl_xor_sync(hm, mx, off, 16));
        float wt0 = li < deg ? __expf(e0 - mx) : 0.f;
        sew[w][half][li] = make_float2(__int_as_float(s0), wt0);
        if (deg > 16) {
            float wt1 = (li + 16) < deg ? __expf(e1 - mx) : 0.f;
            sew[w][half][li + 16] = make_float2(__int_as_float(s1), wt1);
        }
        __syncwarp(hm);

        float ax = 0.f, ay = 0.f, az = 0.f, aw = 0.f;
        float den = 0.f;
        int iters = (deg + 3) >> 2;
        for (int it = 0; it < iters; it++) {
            int base = it * 4;
            float2 p0 = sew[w][half][base + 0];
            float2 p1 = sew[w][half][base + 1];
            float2 p2 = sew[w][half][base + 2];
            float2 p3 = sew[w][half][base + 3];
            uint2 h0 = ((const uint2*)(d_hh + __float_as_int(p0.x) * 64))[li];
            uint2 h1 = ((const uint2*)(d_hh + __float_as_int(p1.x) * 64))[li];
            uint2 h2 = ((const uint2*)(d_hh + __float_as_int(p2.x) * 64))[li];
            uint2 h3 = ((const uint2*)(d_hh + __float_as_int(p3.x) * 64))[li];
            den += (p0.y + p1.y) + (p2.y + p3.y);
            {
                float2 lo = __half22float2(*(__half2*)&h0.x);
                float2 hi = __half22float2(*(__half2*)&h0.y);
                ax += p0.y * lo.x; ay += p0.y * lo.y;
                az += p0.y * hi.x; aw += p0.y * hi.y;
            }
            {
                float2 lo = __half22float2(*(__half2*)&h1.x);
                float2 hi = __half22float2(*(__half2*)&h1.y);
                ax += p1.y * lo.x; ay += p1.y * lo.y;
                az += p1.y * hi.x; aw += p1.y * hi.y;
            }
            {
                float2 lo = __half22float2(*(__half2*)&h2.x);
                float2 hi = __half22float2(*(__half2*)&h2.y);
                ax += p2.y * lo.x; ay += p2.y * lo.y;
                az += p2.y * hi.x; aw += p2.y * hi.y;
            }
            {
                float2 lo = __half22float2(*(__half2*)&h3.x);
                float2 hi = __half22float2(*(__half2*)&h3.y);
                ax += p3.y * lo.x; ay += p3.y * lo.y;
                az += p3.y * hi.x; aw += p3.y * hi.y;
            }
        }
        float inv = 1.f / (den + 1e-16f);   // deg==0: den=0 -> acc=0 -> out=bias
        float4 r;
        r.x = ax * inv + b4.x;
        r.y = ay * inv + b4.y;
        r.z = az * inv + b4.z;
        r.w = aw * inv + b4.w;
        *op = r;
    } else {
        // essentially-never path (deg in (32,128]), self-contained, half-masked
        float adv = d_adst[node];
        float mx = -CUDART_INF_F;
        for (int j = li; j < deg; j += 16) {
            float e = d_asrc[row[j]] + adv;
            e = e > 0.f ? e : 0.2f * e;
            mx = fmaxf(mx, e);
        }
#pragma unroll
        for (int off = 8; off; off >>= 1)
            mx = fmaxf(mx, __shfl_xor_sync(hm, mx, off, 16));
        float sm = 0.f;
        for (int j = li; j < deg; j += 16) {
            float e = d_asrc[row[j]] + adv;
            e = e > 0.f ? e : 0.2f * e;
            sm += __expf(e - mx);
        }
#pragma unroll
        for (int off = 8; off; off >>= 1)
            sm += __shfl_xor_sync(hm, sm, off, 16);
        float inv = 1.f / (sm + 1e-16f);

        float ax = 0.f, ay = 0.f, az = 0.f, aw = 0.f;
        for (int j = 0; j < deg; j++) {
            int s = row[j];
            float e = d_asrc[s] + adv;
            e = e > 0.f ? e : 0.2f * e;
            float wt = __expf(e - mx);
            uint2 hv = ((const uint2*)(d_hh + s * 64))[li];
            float2 lo = __half22float2(*(__half2*)&hv.x);
            float2 hi = __half22float2(*(__half2*)&hv.y);
            ax += wt * lo.x; ay += wt * lo.y;
            az += wt * hi.x; aw += wt * hi.y;
        }
        float4 r;
        r.x = ax * inv + b4.x;
        r.y = ay * inv + b4.y;
        r.z = az * inv + b4.z;
        r.w = aw * inv + b4.w;
        *op = r;
    }
}

// ================= launch =================

extern "C" void kernel_launch(void* const* d_in, const int* in_sizes, int n_in,
                              void* d_out, int out_size)
{
    const float* g     = (const float*)d_in[0];
    const int*   ei    = (const int*)  d_in[1];
    const float* W     = (const float*)d_in[2];
    const float* att_s = (const float*)d_in[3];
    const float* att_d = (const float*)d_in[4];
    const float* bias  = (const float*)d_in[5];
    float* out = (float*)d_out;

    const int* src = ei;
    const int* dst = ei + NE;

    zero_k<<<(NN + 255) / 256, 256>>>();
    ell_k<<<(NE + 255) / 256, 256>>>(src, dst);

    const int gemm_blocks = (NN + 127) / 128;   // 782
    const int agg_blocks  = NN / 16;            // 6250, exact

    for (int L = 0; L < 4; L++) {
        gemm_attn_k<<<gemm_blocks, 256>>>(L == 0 ? g : nullptr, L == 0 ? 0 : 1,
                                          W, att_s, att_d);
        aggregate_k<<<agg_blocks, 256>>>(bias, L == 3 ? out : nullptr,
                                         L == 3 ? 0 : 1);
    }
}